// round 5
// baseline (speedup 1.0000x reference)
#include <cuda_runtime.h>
#include <cstdint>

// ---------------------------------------------------------------------------
// Problem constants
// ---------------------------------------------------------------------------
constexpr int    N_USERS = 100000;
constexpr int    DIM     = 128;
constexpr size_t SEG     = (size_t)N_USERS * DIM;
constexpr int    NROWS   = 100000;
constexpr int    NSLOT   = 4;
constexpr int    CAP     = 64;

__device__ float g_scratch[(size_t)NSLOT * NROWS * DIM];
__device__ int  g_cnt[NSLOT * NROWS];
__device__ int2 g_bucket[(size_t)NSLOT * NROWS * CAP];

// ---------------------------------------------------------------------------
// f32x2 packed-FMA helpers
// ---------------------------------------------------------------------------
__device__ __forceinline__ unsigned long long pk2(float x, float y) {
    unsigned long long r;
    asm("mov.b64 %0, {%1, %2};" : "=l"(r) : "r"(__float_as_uint(x)), "r"(__float_as_uint(y)));
    return r;
}
__device__ __forceinline__ unsigned long long fma2(unsigned long long a,
                                                   unsigned long long b,
                                                   unsigned long long c) {
    unsigned long long d;
    asm("fma.rn.f32x2 %0, %1, %2, %3;" : "=l"(d) : "l"(a), "l"(b), "l"(c));
    return d;
}
__device__ __forceinline__ void upk2(unsigned long long v, float& lo, float& hi) {
    uint32_t a, b;
    asm("mov.b64 {%0, %1}, %2;" : "=r"(a), "=r"(b) : "l"(v));
    lo = __uint_as_float(a); hi = __uint_as_float(b);
}

// ---------------------------------------------------------------------------
// Kernel 1: zero counters
// ---------------------------------------------------------------------------
__global__ void zero_cnt() {
    int i = blockIdx.x * blockDim.x + threadIdx.x;
    if (i < NSLOT * NROWS) g_cnt[i] = 0;
}

// ---------------------------------------------------------------------------
// Kernel 2: scatter nnz into per-row buckets (unchanged — validated R4)
// ---------------------------------------------------------------------------
__global__ void __launch_bounds__(256) scatter_nnz(
    const int* __restrict__ r0, const int* __restrict__ c0, const float* __restrict__ v0,
    const int* __restrict__ r1, const int* __restrict__ c1, const float* __restrict__ v1,
    const int* __restrict__ r2, const int* __restrict__ c2, const float* __restrict__ v2,
    const int* __restrict__ r3, const int* __restrict__ c3, const float* __restrict__ v3,
    int nnz)
{
    const int slot = blockIdx.y;
    const int* rows; const int* cols; const float* vals;
    switch (slot) {
        case 0:  rows = r0; cols = c0; vals = v0; break;
        case 1:  rows = r1; cols = c1; vals = v1; break;
        case 2:  rows = r2; cols = c2; vals = v2; break;
        default: rows = r3; cols = c3; vals = v3; break;
    }
    const int i = blockIdx.x * 256 + threadIdx.x;
    if (i >= nnz) return;
    const int   row = rows[i];
    const int   col = cols[i];
    const float val = vals[i];
    const int gr  = slot * NROWS + row;
    const int pos = atomicAdd(&g_cnt[gr], 1);
    if (pos < CAP)
        g_bucket[(size_t)gr * CAP + pos] = make_int2(col, __float_as_int(val));
}

// ---------------------------------------------------------------------------
// Kernel 3: gather — one warp per output row (unchanged — validated R4)
// ---------------------------------------------------------------------------
__global__ void __launch_bounds__(256) gather_rows(const float* __restrict__ ebs)
{
    const int wg   = (blockIdx.x * 256 + threadIdx.x) >> 5;
    const int lane = threadIdx.x & 31;
    if (wg >= NSLOT * NROWS) return;

    int cnt = g_cnt[wg];
    cnt = min(cnt, CAP);

    const int2* bk = g_bucket + (size_t)wg * CAP;
    int2 e0 = make_int2(0, 0), e1 = make_int2(0, 0);
    if (lane      < cnt) e0 = bk[lane];
    if (lane + 32 < cnt) e1 = bk[lane + 32];

    float4 acc = make_float4(0.f, 0.f, 0.f, 0.f);
    for (int j = 0; j < cnt; j++) {
        int cj, vb;
        if (j < 32) { cj = __shfl_sync(0xffffffffu, e0.x, j);
                      vb = __shfl_sync(0xffffffffu, e0.y, j); }
        else        { cj = __shfl_sync(0xffffffffu, e1.x, j - 32);
                      vb = __shfl_sync(0xffffffffu, e1.y, j - 32); }
        const float  vj = __int_as_float(vb);
        const float4 e  = *reinterpret_cast<const float4*>(ebs + (size_t)cj * DIM + lane * 4);
        acc.x += vj * e.x; acc.y += vj * e.y; acc.z += vj * e.z; acc.w += vj * e.w;
    }
    *reinterpret_cast<float4*>(g_scratch + (size_t)wg * DIM + lane * 4) = acc;
}

// ---------------------------------------------------------------------------
// Kernel 4: fused fold GEMM, f32x2 FMA, 64-row block tile (8x4 microtile).
//   out = leaky( LI @ Ws + (L*ent) @ Wd )
// ---------------------------------------------------------------------------
constexpr int TR = 64;                         // rows per block
constexpr int GEMM_SMEM = 2 * TR * DIM * 4;    // As + Bs = 64 KB

__global__ void __launch_bounds__(256) fold_gemm3(
    const float* __restrict__ ebs,
    const float* __restrict__ Wsu, const float* __restrict__ Wdu,
    const float* __restrict__ Wsi, const float* __restrict__ Wdi,
    float* __restrict__ outp)
{
    extern __shared__ float sm[];
    float (*As)[DIM] = reinterpret_cast<float(*)[DIM]>(sm);            // LI rows
    float (*Bs)[DIM] = reinterpret_cast<float(*)[DIM]>(sm + TR * DIM); // (L*ent) rows

    const int fold = blockIdx.y;
    const float* LI  = g_scratch + (size_t)(2 * fold)     * SEG;
    const float* L   = g_scratch + (size_t)(2 * fold + 1) * SEG;
    const float* ent = ebs  + (size_t)fold * SEG;
    const float* Ws  = fold ? Wsi : Wsu;
    const float* Wd  = fold ? Wdi : Wdu;
    float* out       = outp + (size_t)fold * SEG;

    const int row0 = blockIdx.x * TR;
    const int tid  = threadIdx.x;

    // Cooperative load: 64 rows x 128 cols, float4, row-guarded.
    for (int i = tid; i < TR * (DIM / 4); i += 256) {
        const int rr = i >> 5;
        const int c4 = i & 31;
        const int grow = row0 + rr;
        float4 li = make_float4(0.f, 0.f, 0.f, 0.f);
        float4 b  = li;
        if (grow < N_USERS) {
            const size_t g = (size_t)grow * DIM + c4 * 4;
            li = *reinterpret_cast<const float4*>(LI  + g);
            const float4 ll = *reinterpret_cast<const float4*>(L   + g);
            const float4 ee = *reinterpret_cast<const float4*>(ent + g);
            b = make_float4(ll.x * ee.x, ll.y * ee.y, ll.z * ee.z, ll.w * ee.w);
        }
        *reinterpret_cast<float4*>(&As[rr][c4 * 4]) = li;
        *reinterpret_cast<float4*>(&Bs[rr][c4 * 4]) = b;
    }
    __syncthreads();

    const int tx = tid & 31;    // cols 4*tx .. 4*tx+3
    const int ty = tid >> 5;    // rows 8*ty .. 8*ty+7

    unsigned long long acc2[8][2];
    #pragma unroll
    for (int r = 0; r < 8; r++) { acc2[r][0] = 0ull; acc2[r][1] = 0ull; }

    #pragma unroll 2
    for (int kb = 0; kb < DIM; kb += 4) {
        // Prefetch W rows for this 4-k block: 4 k x 2 mats x 2 u64 pairs.
        ulonglong2 wsp[4], wdp[4];
        #pragma unroll
        for (int kk = 0; kk < 4; kk++) {
            wsp[kk] = *reinterpret_cast<const ulonglong2*>(Ws + (size_t)(kb + kk) * DIM + tx * 4);
            wdp[kk] = *reinterpret_cast<const ulonglong2*>(Wd + (size_t)(kb + kk) * DIM + tx * 4);
        }
        #pragma unroll
        for (int r = 0; r < 8; r++) {
            const float4 a4 = *reinterpret_cast<const float4*>(&As[ty * 8 + r][kb]);  // LDS broadcast
            const float4 b4 = *reinterpret_cast<const float4*>(&Bs[ty * 8 + r][kb]);
            const float av[4] = {a4.x, a4.y, a4.z, a4.w};
            const float bv[4] = {b4.x, b4.y, b4.z, b4.w};
            #pragma unroll
            for (int kk = 0; kk < 4; kk++) {
                const unsigned long long aa = pk2(av[kk], av[kk]);
                const unsigned long long bb = pk2(bv[kk], bv[kk]);
                acc2[r][0] = fma2(aa, wsp[kk].x, acc2[r][0]);
                acc2[r][1] = fma2(aa, wsp[kk].y, acc2[r][1]);
                acc2[r][0] = fma2(bb, wdp[kk].x, acc2[r][0]);
                acc2[r][1] = fma2(bb, wdp[kk].y, acc2[r][1]);
            }
        }
    }

    #pragma unroll
    for (int r = 0; r < 8; r++) {
        const int grow = row0 + ty * 8 + r;
        if (grow >= N_USERS) break;
        float c0, c1, c2, c3;
        upk2(acc2[r][0], c0, c1);
        upk2(acc2[r][1], c2, c3);
        float4 o;
        o.x = (c0 > 0.f) ? c0 : 0.2f * c0;
        o.y = (c1 > 0.f) ? c1 : 0.2f * c1;
        o.z = (c2 > 0.f) ? c2 : 0.2f * c2;
        o.w = (c3 > 0.f) ? c3 : 0.2f * c3;
        *reinterpret_cast<float4*>(out + (size_t)grow * DIM + tx * 4) = o;
    }
}

// ---------------------------------------------------------------------------
// Launch contract
// ---------------------------------------------------------------------------
extern "C" void kernel_launch(void* const* d_in, const int* in_sizes, int n_in,
                              void* d_out, int out_size)
{
    const float* ebs  = (const float*)d_in[0];
    const float* Wsu  = (const float*)d_in[1];
    const float* Wdu  = (const float*)d_in[2];
    const float* Wsi  = (const float*)d_in[3];
    const float* Wdi  = (const float*)d_in[4];
    const float* vLIu = (const float*)d_in[5];
    const float* vLu  = (const float*)d_in[6];
    const float* vLIi = (const float*)d_in[7];
    const float* vLi  = (const float*)d_in[8];
    const int* rLIu = (const int*)d_in[9];
    const int* cLIu = (const int*)d_in[10];
    const int* rLu  = (const int*)d_in[11];
    const int* cLu  = (const int*)d_in[12];
    const int* rLIi = (const int*)d_in[13];
    const int* cLIi = (const int*)d_in[14];
    const int* rLi  = (const int*)d_in[15];
    const int* cLi  = (const int*)d_in[16];
    float* out = (float*)d_out;

    const int nnz = in_sizes[5];

    // 1) zero counters
    zero_cnt<<<(NSLOT * NROWS + 255) / 256, 256>>>();

    // 2) scatter nnz into buckets
    {
        dim3 grid((nnz + 255) / 256, NSLOT);
        scatter_nnz<<<grid, 256>>>(rLIu, cLIu, vLIu,
                                   rLu,  cLu,  vLu,
                                   rLIi, cLIi, vLIi,
                                   rLi,  cLi,  vLi,
                                   nnz);
    }

    // 3) gather
    {
        const int total_warps = NSLOT * NROWS;
        const int blocks = (total_warps * 32 + 255) / 256;
        gather_rows<<<blocks, 256>>>(ebs);
    }

    // 4) fused fold GEMM, 64-row tiles
    {
        cudaFuncSetAttribute(fold_gemm3,
                             cudaFuncAttributeMaxDynamicSharedMemorySize, GEMM_SMEM);
        dim3 grid((N_USERS + TR - 1) / TR, 2);
        fold_gemm3<<<grid, 256, GEMM_SMEM>>>(ebs, Wsu, Wdu, Wsi, Wdi, out);
    }
}